// round 7
// baseline (speedup 1.0000x reference)
#include <cuda_runtime.h>
#include <cstdint>

#define CAP 2097152   // >= BATCH (2,000,000)

// ---------------- device scratch (no allocation allowed) ----------------
__device__ int2 g_list[3][CAP];   // (row, xi) per group
__device__ int  g_counts[3];

// packed fp32x2 FMA
__device__ __forceinline__ void ffma2(float2& d, float2 a, float2 b) {
    asm("fma.rn.f32x2 %0, %1, %2, %0;"
        : "+l"(reinterpret_cast<unsigned long long&>(d))
        : "l"(reinterpret_cast<const unsigned long long&>(a)),
          "l"(reinterpret_cast<const unsigned long long&>(b)));
}

// ---------------- kernel 0: reset counters ----------------
__global__ void reset_k() {
    if (threadIdx.x < 3) g_counts[threadIdx.x] = 0;
}

// ---------------- kernel 1: compact rows by group ----------------
__global__ __launch_bounds__(256)
void compact_k(const int* __restrict__ x, const int* __restrict__ grp, int B) {
    __shared__ int s_cnt[3], s_base[3];
    const int tid = threadIdx.x;
    for (long long base = (long long)blockIdx.x * 256; base < B;
         base += (long long)gridDim.x * 256) {
        if (tid < 3) s_cnt[tid] = 0;
        __syncthreads();
        const long long row = base + tid;
        int g = -1, xi = 0, pos = -1;
        if (row < B) {
            g  = __ldg(grp + row);
            xi = __ldg(x + row);
            if ((unsigned)g < 3u) pos = atomicAdd(&s_cnt[g], 1);
        }
        __syncthreads();
        if (tid < 3) s_base[tid] = atomicAdd(&g_counts[tid], s_cnt[tid]);
        __syncthreads();
        if (pos >= 0) g_list[g][s_base[g] + pos] = make_int2((int)row, xi);
        __syncthreads();
    }
}

// ---------------- fused kernel: block-role specialization ----------------
#define HEAD_BLOCKS 512
#define MID_BLOCKS  448
#define TAIL_BLOCKS 224
#define FUSED_BLOCKS (HEAD_BLOCKS + MID_BLOCKS + TAIL_BLOCKS)

__global__ __launch_bounds__(256, 2)
void fused_k(const float* __restrict__ head,
             const float* __restrict__ mid,
             const float* __restrict__ tail,
             const float* __restrict__ Wm,
             const float* __restrict__ bm,
             const float* __restrict__ Wt,
             const float* __restrict__ bt,
             float*       __restrict__ out)
{
    const int t = threadIdx.x;
    int b = blockIdx.x;

    if (b < HEAD_BLOCKS) {
        // ---------- HEAD: pure gather-copy, 16 threads x float4 per row ----------
        const int n      = g_counts[0];
        const int seg    = t & 15;
        const int stride = (HEAD_BLOCKS * 256) >> 4;
        int i = (b * 256 + t) >> 4;
        // 2-row unroll for MLP
        for (; i + stride < n; i += 2 * stride) {
            const int2 e0 = __ldg(&g_list[0][i]);
            const int2 e1 = __ldg(&g_list[0][i + stride]);
            const float4 v0 = __ldg((const float4*)(head + (size_t)e0.y * 64) + seg);
            const float4 v1 = __ldg((const float4*)(head + (size_t)e1.y * 64) + seg);
            __stcs((float4*)(out + (size_t)e0.x * 64) + seg, v0);
            __stcs((float4*)(out + (size_t)e1.x * 64) + seg, v1);
        }
        if (i < n) {
            const int2 e0 = __ldg(&g_list[0][i]);
            const float4 v0 = __ldg((const float4*)(head + (size_t)e0.y * 64) + seg);
            __stcs((float4*)(out + (size_t)e0.x * 64) + seg, v0);
        }
    } else if (b < HEAD_BLOCKS + MID_BLOCKS) {
        // ---------- MID: warp per row, thread owns j=lane and j=lane+32 ----------
        b -= HEAD_BLOCKS;
        const int n      = g_counts[1];
        const int lane   = t & 31;
        const int nwarps = (MID_BLOCKS * 256) >> 5;
        float2 w0[16], w1[16];
#pragma unroll
        for (int q = 0; q < 16; q++) {
            w0[q] = __ldg((const float2*)(Wm + (size_t)lane * 32) + q);
            w1[q] = __ldg((const float2*)(Wm + (size_t)(lane + 32) * 32) + q);
        }
        const float b0 = __ldg(bm + lane);
        const float b1 = __ldg(bm + lane + 32);

        for (int i = (b * 256 + t) >> 5; i < n; i += nwarps) {
            const int2 e = __ldg(&g_list[1][i]);      // warp-broadcast
            const float4* v4 = (const float4*)(mid + (size_t)e.y * 32);
            float2 a0 = make_float2(b0, 0.f), a1 = make_float2(b1, 0.f);
            // two batches of 4 broadcast LDG.128 (MLP=4) to bound live registers
#pragma unroll
            for (int h = 0; h < 2; h++) {
                float4 v[4];
#pragma unroll
                for (int q = 0; q < 4; q++) v[q] = __ldg(v4 + 4 * h + q);
#pragma unroll
                for (int q = 0; q < 4; q++) {
                    const int qq = 4 * h + q;
                    const float2 lo = make_float2(v[q].x, v[q].y);
                    const float2 hi = make_float2(v[q].z, v[q].w);
                    ffma2(a0, lo, w0[2 * qq]);
                    ffma2(a0, hi, w0[2 * qq + 1]);
                    ffma2(a1, lo, w1[2 * qq]);
                    ffma2(a1, hi, w1[2 * qq + 1]);
                }
            }
            float* o = out + (size_t)e.x * 64;
            __stcs(o + lane,      a0.x + a0.y);   // warp: 128B contiguous
            __stcs(o + 32 + lane, a1.x + a1.y);   // warp: 128B contiguous
        }
    } else {
        // ---------- TAIL: warp per row, thread owns j=lane and j=lane+32 ----------
        b -= HEAD_BLOCKS + MID_BLOCKS;
        const int n      = g_counts[2];
        const int lane   = t & 31;
        const int nwarps = (TAIL_BLOCKS * 256) >> 5;
        float2 w0[8], w1[8];
#pragma unroll
        for (int q = 0; q < 8; q++) {
            w0[q] = __ldg((const float2*)(Wt + (size_t)lane * 16) + q);
            w1[q] = __ldg((const float2*)(Wt + (size_t)(lane + 32) * 16) + q);
        }
        const float b0 = __ldg(bt + lane);
        const float b1 = __ldg(bt + lane + 32);

        for (int i = (b * 256 + t) >> 5; i < n; i += nwarps) {
            const int2 e = __ldg(&g_list[2][i]);
            const float4* v4 = (const float4*)(tail + (size_t)e.y * 16);
            float4 v[4];
#pragma unroll
            for (int q = 0; q < 4; q++) v[q] = __ldg(v4 + q);
            float2 a0 = make_float2(b0, 0.f), a1 = make_float2(b1, 0.f);
#pragma unroll
            for (int q = 0; q < 4; q++) {
                const float2 lo = make_float2(v[q].x, v[q].y);
                const float2 hi = make_float2(v[q].z, v[q].w);
                ffma2(a0, lo, w0[2 * q]);
                ffma2(a0, hi, w0[2 * q + 1]);
                ffma2(a1, lo, w1[2 * q]);
                ffma2(a1, hi, w1[2 * q + 1]);
            }
            float* o = out + (size_t)e.x * 64;
            __stcs(o + lane,      a0.x + a0.y);
            __stcs(o + 32 + lane, a1.x + a1.y);
        }
    }
}

// ---------------- launcher ----------------
extern "C" void kernel_launch(void* const* d_in, const int* in_sizes, int n_in,
                              void* d_out, int out_size)
{
    // metadata order: x, frequency_groups, head_table, mid_table, tail_table,
    //                 W_mid, b_mid, W_tail, b_tail
    const int*   x    = (const int*)  d_in[0];
    const int*   grp  = (const int*)  d_in[1];
    const float* head = (const float*)d_in[2];
    const float* mid  = (const float*)d_in[3];
    const float* tail = (const float*)d_in[4];
    const float* Wm   = (const float*)d_in[5];
    const float* bm   = (const float*)d_in[6];
    const float* Wt   = (const float*)d_in[7];
    const float* bt   = (const float*)d_in[8];
    float* out = (float*)d_out;

    const int B = in_sizes[0];

    reset_k<<<1, 32>>>();
    compact_k<<<2048, 256>>>(x, grp, B);
    fused_k<<<FUSED_BLOCKS, 256>>>(head, mid, tail, Wm, bm, Wt, bt, out);
}

// round 8
// speedup vs baseline: 1.1691x; 1.1691x over previous
#include <cuda_runtime.h>
#include <cstdint>

#define CAP 2097152   // >= BATCH (2,000,000)

// ---------------- device scratch (no allocation allowed) ----------------
__device__ int2 g_list[3][CAP];   // (row, xi) per group
__device__ int  g_counts[3];

// packed fp32x2 FMA
__device__ __forceinline__ void ffma2(float2& d, float2 a, float2 b) {
    asm("fma.rn.f32x2 %0, %1, %2, %0;"
        : "+l"(reinterpret_cast<unsigned long long&>(d))
        : "l"(reinterpret_cast<const unsigned long long&>(a)),
          "l"(reinterpret_cast<const unsigned long long&>(b)));
}

// ---------------- kernel 0: reset counters ----------------
__global__ void reset_k() {
    if (threadIdx.x < 3) g_counts[threadIdx.x] = 0;
}

// ---------------- kernel 1: compact rows by group ----------------
__global__ __launch_bounds__(256)
void compact_k(const int* __restrict__ x, const int* __restrict__ grp, int B) {
    __shared__ int s_cnt[3], s_base[3];
    const int tid = threadIdx.x;
    for (long long base = (long long)blockIdx.x * 256; base < B;
         base += (long long)gridDim.x * 256) {
        if (tid < 3) s_cnt[tid] = 0;
        __syncthreads();
        const long long row = base + tid;
        int g = -1, xi = 0, pos = -1;
        if (row < B) {
            g  = __ldg(grp + row);
            xi = __ldg(x + row);
            if ((unsigned)g < 3u) pos = atomicAdd(&s_cnt[g], 1);
        }
        __syncthreads();
        if (tid < 3) s_base[tid] = atomicAdd(&g_counts[tid], s_cnt[tid]);
        __syncthreads();
        if (pos >= 0) g_list[g][s_base[g] + pos] = make_int2((int)row, xi);
        __syncthreads();
    }
}

// ---------------- kernel 2: head = pure gather-copy, 2-row unrolled ----------------
__global__ __launch_bounds__(256)
void head_k(const float* __restrict__ head, float* __restrict__ out) {
    const int n      = g_counts[0];
    const int seg    = threadIdx.x & 15;                 // 16 threads x float4 = row
    const int stride = (gridDim.x * 256) >> 4;
    int i = (blockIdx.x * 256 + threadIdx.x) >> 4;
    for (; i + stride < n; i += 2 * stride) {
        const int2 e0 = __ldg(&g_list[0][i]);
        const int2 e1 = __ldg(&g_list[0][i + stride]);
        const float4 v0 = __ldg((const float4*)(head + (size_t)e0.y * 64) + seg);
        const float4 v1 = __ldg((const float4*)(head + (size_t)e1.y * 64) + seg);
        __stcs((float4*)(out + (size_t)e0.x * 64) + seg, v0);
        __stcs((float4*)(out + (size_t)e1.x * 64) + seg, v1);
    }
    if (i < n) {
        const int2 e0 = __ldg(&g_list[0][i]);
        const float4 v0 = __ldg((const float4*)(head + (size_t)e0.y * 64) + seg);
        __stcs((float4*)(out + (size_t)e0.x * 64) + seg, v0);
    }
}

// ---------------- kernel 3: mid GEMV — warp per row, register W ----------------
__global__ __launch_bounds__(256)
void mid_k(const float* __restrict__ mid, const float* __restrict__ Wm,
           const float* __restrict__ bm, float* __restrict__ out) {
    const int n      = g_counts[1];
    const int lane   = threadIdx.x & 31;
    const int nwarps = (gridDim.x * 256) >> 5;

    float2 w0[16], w1[16];
#pragma unroll
    for (int q = 0; q < 16; q++) {
        w0[q] = __ldg((const float2*)(Wm + (size_t)lane * 32) + q);
        w1[q] = __ldg((const float2*)(Wm + (size_t)(lane + 32) * 32) + q);
    }
    const float b0 = __ldg(bm + lane);
    const float b1 = __ldg(bm + lane + 32);

    int i = (blockIdx.x * 256 + threadIdx.x) >> 5;
    if (i >= n) return;
    int2 e = __ldg(&g_list[1][i]);                 // warp-broadcast
    for (; i < n; i += nwarps) {
        const int inext = i + nwarps;
        const int2 en = (inext < n) ? __ldg(&g_list[1][inext]) : e;  // prefetch
        const float4* v4 = (const float4*)(mid + (size_t)e.y * 32);
        float2 a0 = make_float2(b0, 0.f), a1 = make_float2(b1, 0.f);
#pragma unroll
        for (int h = 0; h < 2; h++) {
            float4 v[4];
#pragma unroll
            for (int q = 0; q < 4; q++) v[q] = __ldg(v4 + 4 * h + q);  // broadcast LDG.128
#pragma unroll
            for (int q = 0; q < 4; q++) {
                const int qq = 4 * h + q;
                const float2 lo = make_float2(v[q].x, v[q].y);
                const float2 hi = make_float2(v[q].z, v[q].w);
                ffma2(a0, lo, w0[2 * qq]);
                ffma2(a0, hi, w0[2 * qq + 1]);
                ffma2(a1, lo, w1[2 * qq]);
                ffma2(a1, hi, w1[2 * qq + 1]);
            }
        }
        float* o = out + (size_t)e.x * 64;
        __stcs(o + lane,      a0.x + a0.y);        // warp: 128B contiguous
        __stcs(o + 32 + lane, a1.x + a1.y);
        e = en;
    }
}

// ---------------- kernel 4: tail GEMV — warp per row, register W ----------------
__global__ __launch_bounds__(256)
void tail_k(const float* __restrict__ tail, const float* __restrict__ Wt,
            const float* __restrict__ bt, float* __restrict__ out) {
    const int n      = g_counts[2];
    const int lane   = threadIdx.x & 31;
    const int nwarps = (gridDim.x * 256) >> 5;

    float2 w0[8], w1[8];
#pragma unroll
    for (int q = 0; q < 8; q++) {
        w0[q] = __ldg((const float2*)(Wt + (size_t)lane * 16) + q);
        w1[q] = __ldg((const float2*)(Wt + (size_t)(lane + 32) * 16) + q);
    }
    const float b0 = __ldg(bt + lane);
    const float b1 = __ldg(bt + lane + 32);

    int i = (blockIdx.x * 256 + threadIdx.x) >> 5;
    if (i >= n) return;
    int2 e = __ldg(&g_list[2][i]);
    for (; i < n; i += nwarps) {
        const int inext = i + nwarps;
        const int2 en = (inext < n) ? __ldg(&g_list[2][inext]) : e;
        const float4* v4 = (const float4*)(tail + (size_t)e.y * 16);
        float4 v[4];
#pragma unroll
        for (int q = 0; q < 4; q++) v[q] = __ldg(v4 + q);
        float2 a0 = make_float2(b0, 0.f), a1 = make_float2(b1, 0.f);
#pragma unroll
        for (int q = 0; q < 4; q++) {
            const float2 lo = make_float2(v[q].x, v[q].y);
            const float2 hi = make_float2(v[q].z, v[q].w);
            ffma2(a0, lo, w0[2 * q]);
            ffma2(a0, hi, w0[2 * q + 1]);
            ffma2(a1, lo, w1[2 * q]);
            ffma2(a1, hi, w1[2 * q + 1]);
        }
        float* o = out + (size_t)e.x * 64;
        __stcs(o + lane,      a0.x + a0.y);
        __stcs(o + 32 + lane, a1.x + a1.y);
        e = en;
    }
}

// ---------------- launcher ----------------
extern "C" void kernel_launch(void* const* d_in, const int* in_sizes, int n_in,
                              void* d_out, int out_size)
{
    // metadata order: x, frequency_groups, head_table, mid_table, tail_table,
    //                 W_mid, b_mid, W_tail, b_tail
    const int*   x    = (const int*)  d_in[0];
    const int*   grp  = (const int*)  d_in[1];
    const float* head = (const float*)d_in[2];
    const float* mid  = (const float*)d_in[3];
    const float* tail = (const float*)d_in[4];
    const float* Wm   = (const float*)d_in[5];
    const float* bm   = (const float*)d_in[6];
    const float* Wt   = (const float*)d_in[7];
    const float* bt   = (const float*)d_in[8];
    float* out = (float*)d_out;

    const int B = in_sizes[0];

    reset_k  <<<1, 32>>>();
    compact_k<<<2048, 256>>>(x, grp, B);
    head_k   <<<2048, 256>>>(head, out);
    mid_k    <<<2048, 256>>>(mid,  Wm, bm, out);
    tail_k   <<<2048, 256>>>(tail, Wt, bt, out);
}

// round 9
// speedup vs baseline: 1.7424x; 1.4904x over previous
#include <cuda_runtime.h>
#include <cstdint>

#define CAP 2097152   // >= BATCH (2,000,000)

// ---------------- device scratch (no allocation allowed) ----------------
__device__ int2 g_list[3][CAP];   // (row, xi) per group
__device__ int  g_counts[3];
__device__ int  g_tile[2];        // work-stealing tile counters (mid, tail)

// packed fp32x2 FMA
__device__ __forceinline__ void ffma2(float2& d, float2 a, float2 b) {
    asm("fma.rn.f32x2 %0, %1, %2, %0;"
        : "+l"(reinterpret_cast<unsigned long long&>(d))
        : "l"(reinterpret_cast<const unsigned long long&>(a)),
          "l"(reinterpret_cast<const unsigned long long&>(b)));
}

// ---------------- kernel 0: reset counters ----------------
__global__ void reset_k() {
    if (threadIdx.x < 3) g_counts[threadIdx.x] = 0;
    if (threadIdx.x < 2) g_tile[threadIdx.x] = 0;
}

// ---------------- kernel 1: compact rows by group ----------------
__global__ __launch_bounds__(256)
void compact_k(const int* __restrict__ x, const int* __restrict__ grp, int B) {
    __shared__ int s_cnt[3], s_base[3];
    const int tid = threadIdx.x;
    for (long long base = (long long)blockIdx.x * 256; base < B;
         base += (long long)gridDim.x * 256) {
        if (tid < 3) s_cnt[tid] = 0;
        __syncthreads();
        const long long row = base + tid;
        int g = -1, xi = 0, pos = -1;
        if (row < B) {
            g  = __ldg(grp + row);
            xi = __ldg(x + row);
            if ((unsigned)g < 3u) pos = atomicAdd(&s_cnt[g], 1);
        }
        __syncthreads();
        if (tid < 3) s_base[tid] = atomicAdd(&g_counts[tid], s_cnt[tid]);
        __syncthreads();
        if (pos >= 0) g_list[g][s_base[g] + pos] = make_int2((int)row, xi);
        __syncthreads();
    }
}

// ---------------- kernel 2: head = pure gather-copy, 2-row unrolled ----------------
__global__ __launch_bounds__(256)
void head_k(const float* __restrict__ head, float* __restrict__ out) {
    const int n      = g_counts[0];
    const int seg    = threadIdx.x & 15;                 // 16 threads x float4 = row
    const int stride = (gridDim.x * 256) >> 4;
    int i = (blockIdx.x * 256 + threadIdx.x) >> 4;
    for (; i + stride < n; i += 2 * stride) {
        const int2 e0 = __ldg(&g_list[0][i]);
        const int2 e1 = __ldg(&g_list[0][i + stride]);
        const float4 v0 = __ldg((const float4*)(head + (size_t)e0.y * 64) + seg);
        const float4 v1 = __ldg((const float4*)(head + (size_t)e1.y * 64) + seg);
        __stcs((float4*)(out + (size_t)e0.x * 64) + seg, v0);
        __stcs((float4*)(out + (size_t)e1.x * 64) + seg, v1);
    }
    if (i < n) {
        const int2 e0 = __ldg(&g_list[0][i]);
        const float4 v0 = __ldg((const float4*)(head + (size_t)e0.y * 64) + seg);
        __stcs((float4*)(out + (size_t)e0.x * 64) + seg, v0);
    }
}

// ---------------- kernel 3: mid GEMV — thread per row, W broadcast from SMEM ----
__global__ __launch_bounds__(256, 2)
void mid_k(const float* __restrict__ mid, const float* __restrict__ Wm,
           const float* __restrict__ bm, float* __restrict__ out) {
    __shared__ float Wt_sh[32][64];   // W^T: Wt_sh[k][j] = Wm[j*32+k], 8KB
    __shared__ float bs[64];

    const int n    = g_counts[1];
    const int t    = threadIdx.x;
    const int lane = t & 31;

    for (int idx = t; idx < 64 * 32; idx += 256) {
        const int j = idx >> 5, k = idx & 31;
        Wt_sh[k][j] = __ldg(Wm + idx);        // coalesced read, transposed write
    }
    if (t < 64) bs[t] = __ldg(bm + t);
    __syncthreads();

    for (;;) {
        int tile;
        if (lane == 0) tile = atomicAdd(&g_tile[0], 1);
        tile = __shfl_sync(0xffffffffu, tile, 0);
        const int base = tile * 32;
        if (base >= n) break;

        const int  i     = base + lane;
        const bool valid = i < n;
        const int2 e = __ldg(&g_list[1][valid ? i : 0]);   // coalesced int2

        // own row: 8 contiguous float4 gathers, MLP=8
        const float4* v4 = (const float4*)(mid + (size_t)e.y * 32);
        float4 v[8];
#pragma unroll
        for (int q = 0; q < 8; q++) v[q] = __ldg(v4 + q);
        const float* vf = (const float*)v;

        // 64 accumulators initialized to bias (broadcast LDS)
        float2 acc[32];
#pragma unroll
        for (int q = 0; q < 16; q++) {
            const float4 bb = *(const float4*)&bs[4 * q];
            acc[2 * q]     = make_float2(bb.x, bb.y);
            acc[2 * q + 1] = make_float2(bb.z, bb.w);
        }

        // k-outer: per k, 16 broadcast LDS.128 of W^T row + 32 FFMA2
#pragma unroll
        for (int k = 0; k < 32; k++) {
            const float  vk  = vf[k];
            const float2 vk2 = make_float2(vk, vk);
#pragma unroll
            for (int q = 0; q < 16; q++) {
                const float4 w = *(const float4*)&Wt_sh[k][4 * q];
                ffma2(acc[2 * q],     vk2, make_float2(w.x, w.y));
                ffma2(acc[2 * q + 1], vk2, make_float2(w.z, w.w));
            }
        }

        if (valid) {
            float4* o = (float4*)(out + (size_t)e.x * 64);
#pragma unroll
            for (int q = 0; q < 16; q++)
                __stcs(o + q, make_float4(acc[2 * q].x, acc[2 * q].y,
                                          acc[2 * q + 1].x, acc[2 * q + 1].y));
        }
    }
}

// ---------------- kernel 4: tail GEMV — thread per row, W broadcast from SMEM ----
__global__ __launch_bounds__(256, 2)
void tail_k(const float* __restrict__ tail, const float* __restrict__ Wt,
            const float* __restrict__ bt, float* __restrict__ out) {
    __shared__ float Wt_sh[16][64];   // W^T: Wt_sh[k][j] = Wt[j*16+k], 4KB
    __shared__ float bs[64];

    const int n    = g_counts[2];
    const int t    = threadIdx.x;
    const int lane = t & 31;

    for (int idx = t; idx < 64 * 16; idx += 256) {
        const int j = idx >> 4, k = idx & 15;
        Wt_sh[k][j] = __ldg(Wt + idx);
    }
    if (t < 64) bs[t] = __ldg(bt + t);
    __syncthreads();

    for (;;) {
        int tile;
        if (lane == 0) tile = atomicAdd(&g_tile[1], 1);
        tile = __shfl_sync(0xffffffffu, tile, 0);
        const int base = tile * 32;
        if (base >= n) break;

        const int  i     = base + lane;
        const bool valid = i < n;
        const int2 e = __ldg(&g_list[2][valid ? i : 0]);

        const float4* v4 = (const float4*)(tail + (size_t)e.y * 16);
        float4 v[4];
#pragma unroll
        for (int q = 0; q < 4; q++) v[q] = __ldg(v4 + q);
        const float* vf = (const float*)v;

        float2 acc[32];
#pragma unroll
        for (int q = 0; q < 16; q++) {
            const float4 bb = *(const float4*)&bs[4 * q];
            acc[2 * q]     = make_float2(bb.x, bb.y);
            acc[2 * q + 1] = make_float2(bb.z, bb.w);
        }

#pragma unroll
        for (int k = 0; k < 16; k++) {
            const float  vk  = vf[k];
            const float2 vk2 = make_float2(vk, vk);
#pragma unroll
            for (int q = 0; q < 16; q++) {
                const float4 w = *(const float4*)&Wt_sh[k][4 * q];
                ffma2(acc[2 * q],     vk2, make_float2(w.x, w.y));
                ffma2(acc[2 * q + 1], vk2, make_float2(w.z, w.w));
            }
        }

        if (valid) {
            float4* o = (float4*)(out + (size_t)e.x * 64);
#pragma unroll
            for (int q = 0; q < 16; q++)
                __stcs(o + q, make_float4(acc[2 * q].x, acc[2 * q].y,
                                          acc[2 * q + 1].x, acc[2 * q + 1].y));
        }
    }
}

// ---------------- launcher ----------------
extern "C" void kernel_launch(void* const* d_in, const int* in_sizes, int n_in,
                              void* d_out, int out_size)
{
    // metadata order: x, frequency_groups, head_table, mid_table, tail_table,
    //                 W_mid, b_mid, W_tail, b_tail
    const int*   x    = (const int*)  d_in[0];
    const int*   grp  = (const int*)  d_in[1];
    const float* head = (const float*)d_in[2];
    const float* mid  = (const float*)d_in[3];
    const float* tail = (const float*)d_in[4];
    const float* Wm   = (const float*)d_in[5];
    const float* bm   = (const float*)d_in[6];
    const float* Wt   = (const float*)d_in[7];
    const float* bt   = (const float*)d_in[8];
    float* out = (float*)d_out;

    const int B = in_sizes[0];

    reset_k  <<<1, 32>>>();
    compact_k<<<2048, 256>>>(x, grp, B);
    head_k   <<<2048, 256>>>(head, out);
    mid_k    <<<1024, 256>>>(mid,  Wm, bm, out);
    tail_k   <<<1024, 256>>>(tail, Wt, bt, out);
}